// round 7
// baseline (speedup 1.0000x reference)
#include <cuda_runtime.h>
#include <cstdint>

// Fixed shapes: points (4, 8192, 3) fp32
#define BATCH     4
#define NPTS      8192
#define NTOT      (BATCH * NPTS)
#define NN_SIZE   16
#define RADIUS2   0.25f
#define EPS_LOSS  1e-4f

// Spatial grid: cell width 0.25 (= radius/2), domain [-5,5) clamped
#define GDIM      40
#define NCELLS    (GDIM * GDIM * GDIM)     // 64000
#define GMIN      (-5.0f)
#define INV_CW    4.0f
#define CW        0.25f

// Binning kernel: 128 blocks x 256 = 32768 threads (one per point), all-resident
#define BIN_GRID  128
#define BIN_TPB   256
#define SCAN_CPT  (NCELLS / BIN_TPB)       // 250 cells per thread (blocks 0..3)

// Main kernel layout
#define SPLIT     4
#define TPB       128
#define QPB       (TPB / SPLIT)            // 32 queries per block
#define BPB       (NPTS / QPB)             // 256 blocks per batch
#define MROW      65                       // conflict-free merge-row stride

__device__ volatile unsigned g_bar;               // grid barrier (reset by k_final)
__device__ int    g_count [BATCH * NCELLS];       // zeroed by scan pass each run
__device__ int    g_start [BATCH * NCELLS];       // excl scan; becomes END after scatter
__device__ float4 g_sorted[NTOT];
__device__ int    g_sid   [NTOT];                 // sorted pos -> original index
__device__ float  g_loss  [NTOT];                 // per ORIGINAL index (deterministic)

__device__ __forceinline__ int cell_of(float x, float y, float z) {
    int cx = (int)floorf((x - GMIN) * INV_CW);
    int cy = (int)floorf((y - GMIN) * INV_CW);
    int cz = (int)floorf((z - GMIN) * INV_CW);
    cx = min(max(cx, 0), GDIM - 1);
    cy = min(max(cy, 0), GDIM - 1);
    cz = min(max(cz, 0), GDIM - 1);
    return (cz * GDIM + cy) * GDIM + cx;
}

// Grid-wide barrier: monotonic arrive counter, per-phase target. All BIN_GRID
// blocks are guaranteed concurrently resident (128 blocks x 256 thr).
__device__ __forceinline__ void gbar(unsigned target) {
    __syncthreads();
    if (threadIdx.x == 0) {
        __threadfence();
        atomicAdd((unsigned*)&g_bar, 1u);
        while (g_bar < target) { __nanosleep(40); }
    }
    __syncthreads();
}

// Fused binning: count -> barrier -> scan(+zero counts) -> barrier -> scatter.
__global__ __launch_bounds__(BIN_TPB) void k_bin(const float* __restrict__ pts) {
    const int tid = blockIdx.x * BIN_TPB + threadIdx.x;   // point index, exactly NTOT threads
    const int b   = tid >> 13;                            // tid / NPTS

    // Phase 1: count (g_count was zeroed by previous run's scan / initial zero-init)
    const float x = pts[3 * tid + 0];
    const float y = pts[3 * tid + 1];
    const float z = pts[3 * tid + 2];
    const int   c = cell_of(x, y, z);
    atomicAdd(&g_count[b * NCELLS + c], 1);

    gbar(BIN_GRID);

    // Phase 2: exclusive scan per batch (blocks 0..3), two-pass register-light.
    if (blockIdx.x < BATCH) {
        const int sb   = blockIdx.x;
        const int t    = threadIdx.x;
        const int lane = t & 31, warp = t >> 5;
        const int base = sb * NCELLS + t * SCAN_CPT;
        __shared__ int wsum[BIN_TPB / 32];

        int tot = 0;
        for (int i = 0; i < SCAN_CPT; ++i) tot += g_count[base + i];

        int inc = tot;
#pragma unroll
        for (int off = 1; off < 32; off <<= 1) {
            int n = __shfl_up_sync(0xffffffffu, inc, off);
            if (lane >= off) inc += n;
        }
        if (lane == 31) wsum[warp] = inc;
        __syncthreads();
        if (warp == 0 && lane < BIN_TPB / 32) {
            int w = wsum[lane];
#pragma unroll
            for (int off = 1; off < BIN_TPB / 32; off <<= 1) {
                int n = __shfl_up_sync(0xffu, w, off);
                if (lane >= off) w += n;
            }
            wsum[lane] = w;
        }
        __syncthreads();
        int run = inc - tot + (warp ? wsum[warp - 1] : 0);
        for (int i = 0; i < SCAN_CPT; ++i) {
            int v = g_count[base + i];
            g_start[base + i] = run;
            run += v;
            g_count[base + i] = 0;        // self-restore for next run
        }
    }

    gbar(2 * BIN_GRID);

    // Phase 3: scatter; atomic consume of g_start turns it into the END array.
    const int pos = atomicAdd(&g_start[b * NCELLS + c], 1);
    const float w = 0.5f * (x * x + y * y + z * z);
    g_sorted[b * NPTS + pos] = make_float4(x, y, z, w);
    g_sid[b * NPTS + pos] = tid - b * NPTS;
}

__global__ void k_dummy() {}   // ncu alignment (observed offset: -s 5 == our idx 3)

// Branchless sorted insert (ascending), drop a[15].
__device__ __forceinline__ void sorted_insert16(float (&a)[16], float v) {
#pragma unroll
    for (int k = 15; k > 0; --k) {
        a[k] = fminf(fmaxf(v, a[k - 1]), a[k]);
    }
    a[0] = fminf(a[0], v);
}

// Scan one contiguous candidate run [k0,k1); lane takes k0+s, +SPLIT, ...
// Self-exclusion k != g is safe in every row (g only occurs in its own cell).
__device__ __forceinline__ void scan_run(const float4* __restrict__ spts,
                                         int k0, int k1, int s, int g,
                                         float nqx, float nqy, float nqz,
                                         float (&a)[16]) {
    for (int k = k0 + s; k < k1; k += SPLIT) {
        float4 cd = spts[k];
        float e = fmaf(cd.x, nqx, fmaf(cd.y, nqy, fmaf(cd.z, nqz, cd.w)));
        if (e < a[15] && k != g) sorted_insert16(a, e);
    }
}

__global__ __launch_bounds__(TPB) void k_main() {
    __shared__ float mbuf[QPB * MROW];
    __shared__ float qw_s[QPB];

    const int t  = threadIdx.x;
    const int ql = t >> 2;                  // local query 0..31
    const int s  = t & 3;                   // split lane 0..3
    const int b  = blockIdx.x / BPB;
    const int g  = (blockIdx.x % BPB) * QPB + ql;   // sorted query position

    const float4* __restrict__ spts = &g_sorted[b * NPTS];
    const int*    __restrict__ cend = &g_start[b * NCELLS];   // end offsets

    const float4 qp = spts[g];
    const float nqx = -qp.x, nqy = -qp.y, nqz = -qp.z;
    const float ecap = 0.5f * RADIUS2 - qp.w;       // e < ecap  <=>  d^2 < R^2
    if (s == 0) qw_s[ql] = qp.w;

    float a[16];
#pragma unroll
    for (int k = 0; k < 16; ++k) a[k] = ecap;

    // Query cell coords (identical fp formula as binning -> identical cell)
    int cx = (int)floorf((qp.x - GMIN) * INV_CW);
    int cy = (int)floorf((qp.y - GMIN) * INV_CW);
    int cz = (int)floorf((qp.z - GMIN) * INV_CW);
    cx = min(max(cx, 0), GDIM - 1);
    cy = min(max(cy, 0), GDIM - 1);
    cz = min(max(cz, 0), GDIM - 1);

    const int ORD[5] = {0, -1, 1, -2, 2};   // closest rows first (tightens threshold)

    for (int iz = 0; iz < 5; ++iz) {
        int nz = cz + ORD[iz];
        if ((unsigned)nz >= GDIM) continue;
        float zlo = GMIN + (float)nz * CW;
        float zd  = fmaxf(0.0f, fmaxf(zlo - qp.z, qp.z - (zlo + CW)));
        float zd2 = zd * zd;
        if (zd2 >= RADIUS2 + 1e-5f) continue;
        for (int iy = 0; iy < 5; ++iy) {
            int ny = cy + ORD[iy];
            if ((unsigned)ny >= GDIM) continue;
            float ylo = GMIN + (float)ny * CW;
            float yd  = fmaxf(0.0f, fmaxf(ylo - qp.y, qp.y - (ylo + CW)));
            float yz2 = fmaf(yd, yd, zd2);
            if (yz2 >= RADIUS2 + 1e-5f) continue;   // exact row prune (+safe margin)

            // Exact x-extent: |dx| <= sqrt(R^2 - yz^2); inflated -> over-inclusive (safe)
            float xr = sqrtf(fmaxf(RADIUS2 - yz2, 0.0f)) + 1e-3f;
            int xa = (int)floorf((qp.x - xr - GMIN) * INV_CW);
            int xb = (int)floorf((qp.x + xr - GMIN) * INV_CW);
            xa = max(xa, 0);
            xb = min(xb, GDIM - 1);
            if (xa > xb) continue;

            int row = (nz * GDIM + ny) * GDIM;
            int c0 = row + xa;
            int c1 = row + xb;
            int k0 = (c0 == 0) ? 0 : cend[c0 - 1];
            int k1 = cend[c1];
            scan_run(spts, k0, k1, s, g, nqx, nqy, nqz, a);
        }
    }

    // Dump 4 sorted 16-lists per query.
#pragma unroll
    for (int k = 0; k < 16; ++k) {
        mbuf[ql * MROW + (s << 4) + k] = a[k];
    }
    __syncthreads();

    // One thread per query: 16-step 4-way pointer merge, accumulate loss in
    // ascending-e order (deterministic: top-16 multiset is order-independent).
    if (t < QPB) {
        const float* L   = &mbuf[t * MROW];
        const float  w   = qw_s[t];
        const float  cap = 0.5f * RADIUS2 - w;
        float part = 0.0f;
        int p0 = 0, p1 = 16, p2 = 32, p3 = 48;
#pragma unroll 1
        for (int it = 0; it < NN_SIZE; ++it) {
            float h0 = L[p0], h1 = L[p1], h2 = L[p2], h3 = L[p3];
            float m = fminf(fminf(h0, h1), fminf(h2, h3));
            if (m >= cap) break;           // rest are sentinels / out of radius
            part += rsqrtf(fmaf(2.0f, w + m, EPS_LOSS));   // d^2 = 2*(w+e)
            if      (m == h0) ++p0;
            else if (m == h1) ++p1;
            else if (m == h2) ++p2;
            else              ++p3;
        }
        int gq  = (blockIdx.x % BPB) * QPB + t;
        int oid = g_sid[b * NPTS + gq];
        g_loss[b * NPTS + oid] = part;
    }
}

// Deterministic fixed-order reduction; also resets the grid barrier for replay.
__global__ __launch_bounds__(1024) void k_final(float* __restrict__ out) {
    __shared__ float r[1024];
    const int t = threadIdx.x;
    float s = 0.0f;
#pragma unroll
    for (int i = 0; i < NTOT / 1024; ++i) {
        s += g_loss[i * 1024 + t];
    }
    r[t] = s;
    __syncthreads();
#pragma unroll
    for (int off = 512; off > 0; off >>= 1) {
        if (t < off) r[t] += r[t + off];
        __syncthreads();
    }
    if (t == 0) {
        out[0] = r[0] * (1.0f / (float)(NTOT * NN_SIZE));
        g_bar = 0;                          // self-restore barrier for next replay
    }
}

extern "C" void kernel_launch(void* const* d_in, const int* in_sizes, int n_in,
                              void* d_out, int out_size) {
    (void)in_sizes; (void)n_in; (void)out_size;
    const float* pts = (const float*)d_in[0];
    float* out = (float*)d_out;

    k_bin   <<<BIN_GRID, BIN_TPB>>>(pts);    // idx 0
    k_dummy <<<1, 32>>>();                   // idx 1
    k_dummy <<<1, 32>>>();                   // idx 2
    k_main  <<<BATCH * BPB, TPB>>>();        // idx 3  <- ncu -s 5 (observed +2 offset)
    k_final <<<1, 1024>>>(out);              // idx 4
}